// round 10
// baseline (speedup 1.0000x reference)
#include <cuda_runtime.h>
#include <math.h>

#define NB   4
#define NS   1000
#define NU   192
#define NC   200
#define NG5  5
#define NE   20
#define NJ   10      // H1*K1 = 5*2
#define NH2  4
#define NK2  48
#define TOK  8       // tokens per block for the 192x192 gemm kernels
#define TT   8       // t-rows per block in graph attention

// scratch (no allocations allowed in kernel_launch)
__device__ float g_xg [NB*NC*NU];
__device__ float g_q2 [NB*NC*NU];
__device__ float g_k2 [NB*NC*NU];
__device__ float g_v2 [NB*NC*NU];
__device__ float g_att[NB*NC*NU];
__device__ float g_xg1[NB*NC*NU];

typedef unsigned long long u64;

__device__ __forceinline__ float ex2f(float x) {
    float y;
    asm("ex2.approx.f32 %0, %1;" : "=f"(y) : "f"(x));
    return y;
}
__device__ __forceinline__ u64 pack2(float lo, float hi) {
    u64 r; asm("mov.b64 %0, {%1, %2};" : "=l"(r) : "f"(lo), "f"(hi)); return r;
}
__device__ __forceinline__ void unpack2(u64 v, float& lo, float& hi) {
    asm("mov.b64 {%0, %1}, %2;" : "=f"(lo), "=f"(hi) : "l"(v));
}
__device__ __forceinline__ u64 fma2(u64 a, u64 b, u64 c) {
    u64 r; asm("fma.rn.f32x2 %0, %1, %2, %3;" : "=l"(r) : "l"(a), "l"(b), "l"(c)); return r;
}
__device__ __forceinline__ u64 mul2(u64 a, u64 b) {
    u64 r; asm("mul.rn.f32x2 %0, %1, %2;" : "=l"(r) : "l"(a), "l"(b)); return r;
}
__device__ __forceinline__ u64 add2(u64 a, u64 b) {
    u64 r; asm("add.rn.f32x2 %0, %1, %2;" : "=l"(r) : "l"(a), "l"(b)); return r;
}

// ---------------------------------------------------------------------------
// K1: per-(b,c) tiny MHA (5 heads, key_dim 2, seq=U=192) + channel-mean +
//     GroupNorm(per chunk over U) + pos_emb  ->  g_xg[b,c,u]
// grid (C, B), block 192. Single-pass softmax (logits tiny, no max needed).
// Inner loop uses packed f32x2 FMA over a v-transposed k/v smem layout:
// kvT[j][v], rows 0..9 = k_j, rows 10..19 = v_j. 4 v per iteration.
// ---------------------------------------------------------------------------
__global__ __launch_bounds__(NU) void k1_chunk(
    const float* __restrict__ x,
    const float* __restrict__ Wq, const float* __restrict__ bq,
    const float* __restrict__ Wk, const float* __restrict__ bk,
    const float* __restrict__ Wv, const float* __restrict__ bv,
    const float* __restrict__ Wo, const float* __restrict__ bo,
    const float* __restrict__ pos,
    const float* __restrict__ gng, const float* __restrict__ gnb)
{
    const int c = blockIdx.x;
    const int b = blockIdx.y;
    const int u = threadIdx.x;

    __shared__ float xs[NG5][NU];
    __shared__ float wq_s[NE*NJ], wk_s[NE*NJ], wv_s[NE*NJ], wo_s[NJ*NE];
    __shared__ float bq_s[NJ], bk_s[NJ], bv_s[NJ];
    __shared__ float womean_s[NJ];
    __shared__ float bomean_s;
    __shared__ __align__(16) float kvT_s[2*NJ][NU];  // [j][v]: 0..9 k, 10..19 v
    __shared__ float r1_s[6], r2_s[6];

    for (int i = u; i < NG5*NU; i += NU)
        xs[i/NU][i%NU] = x[((size_t)b*NS + (size_t)c*NG5 + i/NU)*NU + (i%NU)];
    for (int i = u; i < NE*NJ; i += NU) {
        wq_s[i] = Wq[c*NE*NJ + i];
        wk_s[i] = Wk[c*NE*NJ + i];
        wv_s[i] = Wv[c*NE*NJ + i];
        wo_s[i] = Wo[c*NE*NJ + i];   // layout [j*20 + d]
    }
    if (u < NJ) { bq_s[u]=bq[c*NJ+u]; bk_s[u]=bk[c*NJ+u]; bv_s[u]=bv[c*NJ+u]; }
    __syncthreads();

    // mean over d of Wo[c,j,d] and bo[c,d] (consumed after the next barrier)
    if (u < NJ) {
        float s = 0.f;
        #pragma unroll
        for (int d = 0; d < NE; d++) s += wo_s[u*NE + d];
        womean_s[u] = s * (1.f/NE);
    }
    if (u == NJ) {
        float s = 0.f;
        for (int d = 0; d < NE; d++) s += bo[c*NE + d];
        bomean_s = s * (1.f/NE);
    }

    const float chv[NG5] = { xs[0][u], xs[1][u], xs[2][u], xs[3][u], xs[4][u] };
    const int pr[NE] = {0,1,0,2,0,3,0,4,1,2,1,3,1,4,2,3,2,4,3,4};
    float hd[NE];
    #pragma unroll
    for (int d = 0; d < NE; d++) hd[d] = chv[pr[d]];

    float qv[NJ], kk[NJ], vv[NJ];
    #pragma unroll
    for (int j = 0; j < NJ; j++) { qv[j]=bq_s[j]; kk[j]=bk_s[j]; vv[j]=bv_s[j]; }
    #pragma unroll
    for (int d = 0; d < NE; d++) {
        const float hv = hd[d];
        #pragma unroll
        for (int j = 0; j < NJ; j++) {
            qv[j] = fmaf(hv, wq_s[d*NJ+j], qv[j]);
            kk[j] = fmaf(hv, wk_s[d*NJ+j], kk[j]);
            vv[j] = fmaf(hv, wv_s[d*NJ+j], vv[j]);
        }
    }
    // fold softmax scale (1/sqrt(2)) and log2(e) into q so the inner loop is
    // dot -> ex2 directly; broadcast q into both packed lanes
    const float QF = 0.70710678118654752f * 1.44269504088896341f;
    u64 qd[NJ];
    #pragma unroll
    for (int j = 0; j < NJ; j++) { qv[j] *= QF; qd[j] = pack2(qv[j], qv[j]); }

    // write transposed k/v: row j, column u (consecutive u -> consecutive
    // addresses within a row: conflict-free stores)
    #pragma unroll
    for (int j = 0; j < NJ; j++) { kvT_s[j][u] = kk[j]; kvT_s[NJ+j][u] = vv[j]; }
    __syncthreads();

    // single-pass softmax accumulate, 4 v per iteration, packed f32x2 math.
    // acp[j] holds (sum over even-v, sum over odd-v); lhp[h] likewise.
    u64 lhp[5] = {0,0,0,0,0};
    u64 acp[NJ] = {0,0,0,0,0,0,0,0,0,0};
    for (int v0 = 0; v0 < NU; v0 += 4) {
        #pragma unroll
        for (int h = 0; h < 5; h++) {
            const ulonglong2 k0 = *reinterpret_cast<const ulonglong2*>(&kvT_s[2*h  ][v0]);
            const ulonglong2 k1 = *reinterpret_cast<const ulonglong2*>(&kvT_s[2*h+1][v0]);
            u64 s01 = fma2(qd[2*h], k0.x, mul2(qd[2*h+1], k1.x));
            u64 s23 = fma2(qd[2*h], k0.y, mul2(qd[2*h+1], k1.y));
            float s0, s1, s2, s3;
            unpack2(s01, s0, s1); unpack2(s23, s2, s3);
            const float p0 = ex2f(s0), p1 = ex2f(s1),
                        p2 = ex2f(s2), p3 = ex2f(s3);
            const u64 pp01 = pack2(p0, p1), pp23 = pack2(p2, p3);
            lhp[h] = add2(lhp[h], add2(pp01, pp23));
            const ulonglong2 v0r = *reinterpret_cast<const ulonglong2*>(&kvT_s[NJ+2*h  ][v0]);
            const ulonglong2 v1r = *reinterpret_cast<const ulonglong2*>(&kvT_s[NJ+2*h+1][v0]);
            acp[2*h]   = fma2(pp01, v0r.x, acp[2*h]);
            acp[2*h]   = fma2(pp23, v0r.y, acp[2*h]);
            acp[2*h+1] = fma2(pp01, v1r.x, acp[2*h+1]);
            acp[2*h+1] = fma2(pp23, v1r.y, acp[2*h+1]);
        }
    }
    float lh[5], ac[NJ];
    #pragma unroll
    for (int h = 0; h < 5; h++) { float lo, hi; unpack2(lhp[h], lo, hi); lh[h] = lo + hi; }
    #pragma unroll
    for (int j = 0; j < NJ; j++) { float lo, hi; unpack2(acp[j], lo, hi); ac[j] = lo + hi; }

    // alpha.mean(-1) folded: mean_d h = sum_g ch/5 ; proj mean via Wo_mean
    float xr = (chv[0]+chv[1]+chv[2]+chv[3]+chv[4]) * 0.2f + bomean_s;
    #pragma unroll
    for (int h = 0; h < 5; h++) {
        float inv = __fdividef(1.f, lh[h]);
        xr = fmaf(ac[2*h]  *inv, womean_s[2*h],   xr);
        xr = fmaf(ac[2*h+1]*inv, womean_s[2*h+1], xr);
    }

    // GroupNorm over U within this (b,c)
    float s1 = xr, s2 = xr*xr;
    #pragma unroll
    for (int o = 16; o > 0; o >>= 1) {
        s1 += __shfl_xor_sync(0xffffffffu, s1, o);
        s2 += __shfl_xor_sync(0xffffffffu, s2, o);
    }
    const int warp = u >> 5;
    if ((u & 31) == 0) { r1_s[warp] = s1; r2_s[warp] = s2; }
    __syncthreads();
    float S1 = 0.f, S2 = 0.f;
    #pragma unroll
    for (int w = 0; w < 6; w++) { S1 += r1_s[w]; S2 += r2_s[w]; }
    const float mu  = S1 * (1.f/NU);
    const float var = S2 * (1.f/NU) - mu*mu;
    const float o   = (xr - mu) * rsqrtf(var + 1e-3f) * gng[c] + gnb[c]
                      + pos[c*NU + u];
    g_xg[((size_t)b*NC + c)*NU + u] = o;
}

// ---------------------------------------------------------------------------
// K2: q2/k2/v2 = xg @ gW{q,k,v} + b   (3x [800,192]@[192,192])
// grid (C/TOK, B), block 192; 8 tokens per block amortize weight reads
// ---------------------------------------------------------------------------
__global__ __launch_bounds__(NU) void k2_qkv(
    const float* __restrict__ gWq, const float* __restrict__ gbq,
    const float* __restrict__ gWk, const float* __restrict__ gbk,
    const float* __restrict__ gWv, const float* __restrict__ gbv)
{
    const int b  = blockIdx.y;
    const int t0 = blockIdx.x * TOK;
    const int u  = threadIdx.x;
    __shared__ float xrow[TOK][NU];
    for (int i = u; i < TOK*NU; i += NU)
        xrow[i/NU][i%NU] = g_xg[((size_t)b*NC + t0 + i/NU)*NU + (i%NU)];
    __syncthreads();

    float qa[TOK], ka[TOK], va[TOK];
    const float bqv = gbq[u], bkv = gbk[u], bvv = gbv[u];
    #pragma unroll
    for (int t = 0; t < TOK; t++) { qa[t]=bqv; ka[t]=bkv; va[t]=bvv; }
    for (int i = 0; i < NU; i++) {
        const float wq = gWq[i*NU+u], wk = gWk[i*NU+u], wv = gWv[i*NU+u];
        #pragma unroll
        for (int t = 0; t < TOK; t++) {
            const float xv = xrow[t][i];
            qa[t] = fmaf(xv, wq, qa[t]);
            ka[t] = fmaf(xv, wk, ka[t]);
            va[t] = fmaf(xv, wv, va[t]);
        }
    }
    #pragma unroll
    for (int t = 0; t < TOK; t++) {
        const size_t off = ((size_t)b*NC + t0 + t)*NU + u;
        g_q2[off] = qa[t]; g_k2[off] = ka[t]; g_v2[off] = va[t];
    }
}

// ---------------------------------------------------------------------------
// K3: graph attention, TT=8 t-rows per block so K/V head-slices are read once
// per 8 rows instead of once per row. grid (C/TT, H2, B), block 256.
// ---------------------------------------------------------------------------
__global__ __launch_bounds__(256) void k3_attn()
{
    const int t0 = blockIdx.x * TT, h = blockIdx.y, b = blockIdx.z;
    const int tid = threadIdx.x;
    __shared__ __align__(16) float q_s[TT][NK2];
    __shared__ float p_s[TT][NC];

    for (int i = tid; i < TT*NK2; i += 256) {
        const int t = i / NK2, k = i % NK2;
        q_s[t][k] = g_q2[((size_t)b*NC + t0 + t)*NU + h*NK2 + k];
    }
    __syncthreads();

    // logits: 8 rows x 200 cols, one (t,s) dot of length 48 per thread-iter
    const float sc = 0.14433756729740645f;   // 1/sqrt(48)
    for (int i = tid; i < TT*NC; i += 256) {
        const int t = i / NC, s = i % NC;
        const float4* kr = reinterpret_cast<const float4*>(
            g_k2 + ((size_t)b*NC + s)*NU + h*NK2);
        const float4* qq = reinterpret_cast<const float4*>(q_s[t]);
        float acc = 0.f;
        #pragma unroll
        for (int j = 0; j < NK2/4; j++) {
            float4 k4 = kr[j], q4 = qq[j];
            acc += q4.x*k4.x + q4.y*k4.y + q4.z*k4.z + q4.w*k4.w;
        }
        p_s[t][s] = acc * sc;
    }
    __syncthreads();

    // softmax per row: warp w owns row w (8 warps)
    {
        const int w = tid >> 5, lane = tid & 31;
        float m = -1e30f;
        for (int s = lane; s < NC; s += 32) m = fmaxf(m, p_s[w][s]);
        #pragma unroll
        for (int o = 16; o > 0; o >>= 1)
            m = fmaxf(m, __shfl_xor_sync(0xffffffffu, m, o));
        float l = 0.f;
        for (int s = lane; s < NC; s += 32) {
            const float e = __expf(p_s[w][s] - m);
            p_s[w][s] = e; l += e;
        }
        #pragma unroll
        for (int o = 16; o > 0; o >>= 1)
            l += __shfl_xor_sync(0xffffffffu, l, o);
        const float inv = __fdividef(1.f, l);
        for (int s = lane; s < NC; s += 32) p_s[w][s] *= inv;
    }
    __syncthreads();

    // AV: out[t, k] = sum_s p[t,s] * V[s, k]
    for (int i = tid; i < TT*NK2; i += 256) {
        const int t = i / NK2, k = i % NK2;
        const float* vb = g_v2 + (size_t)b*NC*NU + h*NK2 + k;
        float acc = 0.f;
        #pragma unroll 4
        for (int s = 0; s < NC; s++)
            acc = fmaf(p_s[t][s], vb[(size_t)s*NU], acc);
        g_att[((size_t)b*NC + t0 + t)*NU + h*NK2 + k] = acc;
    }
}

// ---------------------------------------------------------------------------
// K4: out-proj (att @ gWo + gbo) + residual + LayerNorm1 -> g_xg1
// grid (C/TOK, B), block 192
// ---------------------------------------------------------------------------
__global__ __launch_bounds__(NU) void k4_proj_ln1(
    const float* __restrict__ gWo, const float* __restrict__ gbo,
    const float* __restrict__ ln1g, const float* __restrict__ ln1b)
{
    const int b = blockIdx.y, t0 = blockIdx.x*TOK, u = threadIdx.x;
    __shared__ float arow[TOK][NU];
    __shared__ float r1s[6][TOK], r2s[6][TOK];
    for (int i = u; i < TOK*NU; i += NU)
        arow[i/NU][i%NU] = g_att[((size_t)b*NC + t0 + i/NU)*NU + (i%NU)];
    __syncthreads();

    float acc[TOK];
    const float bv = gbo[u];
    #pragma unroll
    for (int t = 0; t < TOK; t++) acc[t] = bv;
    for (int i = 0; i < NU; i++) {
        const float w = gWo[i*NU + u];
        #pragma unroll
        for (int t = 0; t < TOK; t++) acc[t] = fmaf(arow[t][i], w, acc[t]);
    }
    float y[TOK], s1[TOK], s2[TOK];
    #pragma unroll
    for (int t = 0; t < TOK; t++) {
        y[t] = g_xg[((size_t)b*NC + t0 + t)*NU + u] + acc[t];
        s1[t] = y[t]; s2[t] = y[t]*y[t];
    }
    #pragma unroll
    for (int o = 16; o > 0; o >>= 1) {
        #pragma unroll
        for (int t = 0; t < TOK; t++) {
            s1[t] += __shfl_xor_sync(0xffffffffu, s1[t], o);
            s2[t] += __shfl_xor_sync(0xffffffffu, s2[t], o);
        }
    }
    const int warp = u >> 5;
    if ((u & 31) == 0) {
        #pragma unroll
        for (int t = 0; t < TOK; t++) { r1s[warp][t] = s1[t]; r2s[warp][t] = s2[t]; }
    }
    __syncthreads();
    const float g = ln1g[u], bb = ln1b[u];
    #pragma unroll
    for (int t = 0; t < TOK; t++) {
        float S1 = 0.f, S2 = 0.f;
        #pragma unroll
        for (int w = 0; w < 6; w++) { S1 += r1s[w][t]; S2 += r2s[w][t]; }
        const float mu = S1*(1.f/NU), var = S2*(1.f/NU) - mu*mu;
        g_xg1[((size_t)b*NC + t0 + t)*NU + u] =
            (y[t] - mu) * rsqrtf(var + 1e-3f) * g + bb;
    }
}

// ---------------------------------------------------------------------------
// K5: FFN (W1 -> W2, exact gelu on second dense) + residual + LayerNorm2
// grid (C/TOK, B), block 192
// ---------------------------------------------------------------------------
__global__ __launch_bounds__(NU) void k5_ffn_ln2(
    const float* __restrict__ W1, const float* __restrict__ b1,
    const float* __restrict__ W2, const float* __restrict__ b2,
    const float* __restrict__ ln2g, const float* __restrict__ ln2b,
    float* __restrict__ out)
{
    const int b = blockIdx.y, t0 = blockIdx.x*TOK, u = threadIdx.x;
    __shared__ float xrow[TOK][NU];
    __shared__ float h1[TOK][NU];
    __shared__ float r1s[6][TOK], r2s[6][TOK];
    for (int i = u; i < TOK*NU; i += NU)
        xrow[i/NU][i%NU] = g_xg1[((size_t)b*NC + t0 + i/NU)*NU + (i%NU)];
    __syncthreads();

    float acc[TOK];
    const float bv1 = b1[u];
    #pragma unroll
    for (int t = 0; t < TOK; t++) acc[t] = bv1;
    for (int i = 0; i < NU; i++) {
        const float w = W1[i*NU + u];
        #pragma unroll
        for (int t = 0; t < TOK; t++) acc[t] = fmaf(xrow[t][i], w, acc[t]);
    }
    #pragma unroll
    for (int t = 0; t < TOK; t++) h1[t][u] = acc[t];
    __syncthreads();

    const float bv2 = b2[u];
    #pragma unroll
    for (int t = 0; t < TOK; t++) acc[t] = bv2;
    for (int i = 0; i < NU; i++) {
        const float w = W2[i*NU + u];
        #pragma unroll
        for (int t = 0; t < TOK; t++) acc[t] = fmaf(h1[t][i], w, acc[t]);
    }

    float y[TOK], s1[TOK], s2[TOK];
    #pragma unroll
    for (int t = 0; t < TOK; t++) {
        const float v = acc[t];
        const float gelu = 0.5f * v * (1.f + erff(v * 0.70710678118654752f));
        y[t] = xrow[t][u] + gelu;
        s1[t] = y[t]; s2[t] = y[t]*y[t];
    }
    #pragma unroll
    for (int o = 16; o > 0; o >>= 1) {
        #pragma unroll
        for (int t = 0; t < TOK; t++) {
            s1[t] += __shfl_xor_sync(0xffffffffu, s1[t], o);
            s2[t] += __shfl_xor_sync(0xffffffffu, s2[t], o);
        }
    }
    const int warp = u >> 5;
    if ((u & 31) == 0) {
        #pragma unroll
        for (int t = 0; t < TOK; t++) { r1s[warp][t] = s1[t]; r2s[warp][t] = s2[t]; }
    }
    __syncthreads();
    const float g = ln2g[u], bb = ln2b[u];
    #pragma unroll
    for (int t = 0; t < TOK; t++) {
        float S1 = 0.f, S2 = 0.f;
        #pragma unroll
        for (int w = 0; w < 6; w++) { S1 += r1s[w][t]; S2 += r2s[w][t]; }
        const float mu = S1*(1.f/NU), var = S2*(1.f/NU) - mu*mu;
        out[((size_t)b*NC + t0 + t)*NU + u] =
            (y[t] - mu) * rsqrtf(var + 1e-3f) * g + bb;
    }
}

// ---------------------------------------------------------------------------
extern "C" void kernel_launch(void* const* d_in, const int* in_sizes, int n_in,
                              void* d_out, int out_size)
{
    (void)in_sizes; (void)n_in; (void)out_size;
    const float* x    = (const float*)d_in[0];
    const float* Wq   = (const float*)d_in[1];
    const float* bq   = (const float*)d_in[2];
    const float* Wk   = (const float*)d_in[3];
    const float* bk   = (const float*)d_in[4];
    const float* Wv   = (const float*)d_in[5];
    const float* bv   = (const float*)d_in[6];
    const float* Wo   = (const float*)d_in[7];
    const float* bo   = (const float*)d_in[8];
    const float* pos  = (const float*)d_in[9];
    const float* gWq  = (const float*)d_in[10];
    const float* gbq  = (const float*)d_in[11];
    const float* gWk  = (const float*)d_in[12];
    const float* gbk  = (const float*)d_in[13];
    const float* gWv  = (const float*)d_in[14];
    const float* gbv  = (const float*)d_in[15];
    const float* gWo  = (const float*)d_in[16];
    const float* gbo  = (const float*)d_in[17];
    const float* gng  = (const float*)d_in[18];
    const float* gnb  = (const float*)d_in[19];
    const float* W1   = (const float*)d_in[20];
    const float* b1   = (const float*)d_in[21];
    const float* W2   = (const float*)d_in[22];
    const float* b2   = (const float*)d_in[23];
    const float* ln1g = (const float*)d_in[24];
    const float* ln1b = (const float*)d_in[25];
    const float* ln2g = (const float*)d_in[26];
    const float* ln2b = (const float*)d_in[27];
    float* out = (float*)d_out;

    k1_chunk  <<<dim3(NC, NB),        NU>>>(x, Wq, bq, Wk, bk, Wv, bv, Wo, bo,
                                            pos, gng, gnb);
    k2_qkv    <<<dim3(NC/TOK, NB),    NU>>>(gWq, gbq, gWk, gbk, gWv, gbv);
    k3_attn   <<<dim3(NC/TT, NH2, NB), 256>>>();
    k4_proj_ln1<<<dim3(NC/TOK, NB),   NU>>>(gWo, gbo, ln1g, ln1b);
    k5_ffn_ln2<<<dim3(NC/TOK, NB),    NU>>>(W1, b1, W2, b2, ln2g, ln2b, out);
}

// round 15
// speedup vs baseline: 1.1426x; 1.1426x over previous
#include <cuda_runtime.h>
#include <math.h>

#define NB   4
#define NS   1000
#define NU   192
#define NC   200
#define NG5  5
#define NE   20
#define NJ   10      // H1*K1 = 5*2
#define NH2  4
#define NK2  48
#define TOK  8       // tokens per block for the 192x192 gemm kernels
#define TT   8       // t-rows per block in graph attention

// scratch (no allocations allowed in kernel_launch)
__device__ float g_xg [NB*NC*NU];
__device__ float g_q2 [NB*NC*NU];
__device__ float g_k2 [NB*NC*NU];
__device__ float g_v2 [NB*NC*NU];
__device__ float g_att[NB*NC*NU];
__device__ float g_xg1[NB*NC*NU];

typedef unsigned long long u64;

__device__ __forceinline__ float ex2f(float x) {
    float y;
    asm("ex2.approx.f32 %0, %1;" : "=f"(y) : "f"(x));
    return y;
}
__device__ __forceinline__ u64 pack2(float lo, float hi) {
    u64 r; asm("mov.b64 %0, {%1, %2};" : "=l"(r) : "f"(lo), "f"(hi)); return r;
}
__device__ __forceinline__ void unpack2(u64 v, float& lo, float& hi) {
    asm("mov.b64 {%0, %1}, %2;" : "=f"(lo), "=f"(hi) : "l"(v));
}
__device__ __forceinline__ u64 fma2(u64 a, u64 b, u64 c) {
    u64 r; asm("fma.rn.f32x2 %0, %1, %2, %3;" : "=l"(r) : "l"(a), "l"(b), "l"(c)); return r;
}
__device__ __forceinline__ u64 mul2(u64 a, u64 b) {
    u64 r; asm("mul.rn.f32x2 %0, %1, %2;" : "=l"(r) : "l"(a), "l"(b)); return r;
}
__device__ __forceinline__ u64 add2(u64 a, u64 b) {
    u64 r; asm("add.rn.f32x2 %0, %1, %2;" : "=l"(r) : "l"(a), "l"(b)); return r;
}

// ---------------------------------------------------------------------------
// K1: per-(b,c) tiny MHA + channel-mean + GroupNorm + pos_emb (unchanged)
// ---------------------------------------------------------------------------
__global__ __launch_bounds__(NU) void k1_chunk(
    const float* __restrict__ x,
    const float* __restrict__ Wq, const float* __restrict__ bq,
    const float* __restrict__ Wk, const float* __restrict__ bk,
    const float* __restrict__ Wv, const float* __restrict__ bv,
    const float* __restrict__ Wo, const float* __restrict__ bo,
    const float* __restrict__ pos,
    const float* __restrict__ gng, const float* __restrict__ gnb)
{
    const int c = blockIdx.x;
    const int b = blockIdx.y;
    const int u = threadIdx.x;

    __shared__ float xs[NG5][NU];
    __shared__ float wq_s[NE*NJ], wk_s[NE*NJ], wv_s[NE*NJ], wo_s[NJ*NE];
    __shared__ float bq_s[NJ], bk_s[NJ], bv_s[NJ];
    __shared__ float womean_s[NJ];
    __shared__ float bomean_s;
    __shared__ __align__(16) float kvT_s[2*NJ][NU];  // [j][v]: 0..9 k, 10..19 v
    __shared__ float r1_s[6], r2_s[6];

    for (int i = u; i < NG5*NU; i += NU)
        xs[i/NU][i%NU] = x[((size_t)b*NS + (size_t)c*NG5 + i/NU)*NU + (i%NU)];
    for (int i = u; i < NE*NJ; i += NU) {
        wq_s[i] = Wq[c*NE*NJ + i];
        wk_s[i] = Wk[c*NE*NJ + i];
        wv_s[i] = Wv[c*NE*NJ + i];
        wo_s[i] = Wo[c*NE*NJ + i];   // layout [j*20 + d]
    }
    if (u < NJ) { bq_s[u]=bq[c*NJ+u]; bk_s[u]=bk[c*NJ+u]; bv_s[u]=bv[c*NJ+u]; }
    __syncthreads();

    if (u < NJ) {
        float s = 0.f;
        #pragma unroll
        for (int d = 0; d < NE; d++) s += wo_s[u*NE + d];
        womean_s[u] = s * (1.f/NE);
    }
    if (u == NJ) {
        float s = 0.f;
        for (int d = 0; d < NE; d++) s += bo[c*NE + d];
        bomean_s = s * (1.f/NE);
    }

    const float chv[NG5] = { xs[0][u], xs[1][u], xs[2][u], xs[3][u], xs[4][u] };
    const int pr[NE] = {0,1,0,2,0,3,0,4,1,2,1,3,1,4,2,3,2,4,3,4};
    float hd[NE];
    #pragma unroll
    for (int d = 0; d < NE; d++) hd[d] = chv[pr[d]];

    float qv[NJ], kk[NJ], vv[NJ];
    #pragma unroll
    for (int j = 0; j < NJ; j++) { qv[j]=bq_s[j]; kk[j]=bk_s[j]; vv[j]=bv_s[j]; }
    #pragma unroll
    for (int d = 0; d < NE; d++) {
        const float hv = hd[d];
        #pragma unroll
        for (int j = 0; j < NJ; j++) {
            qv[j] = fmaf(hv, wq_s[d*NJ+j], qv[j]);
            kk[j] = fmaf(hv, wk_s[d*NJ+j], kk[j]);
            vv[j] = fmaf(hv, wv_s[d*NJ+j], vv[j]);
        }
    }
    const float QF = 0.70710678118654752f * 1.44269504088896341f;
    u64 qd[NJ];
    #pragma unroll
    for (int j = 0; j < NJ; j++) { qv[j] *= QF; qd[j] = pack2(qv[j], qv[j]); }

    #pragma unroll
    for (int j = 0; j < NJ; j++) { kvT_s[j][u] = kk[j]; kvT_s[NJ+j][u] = vv[j]; }
    __syncthreads();

    u64 lhp[5] = {0,0,0,0,0};
    u64 acp[NJ] = {0,0,0,0,0,0,0,0,0,0};
    for (int v0 = 0; v0 < NU; v0 += 4) {
        #pragma unroll
        for (int h = 0; h < 5; h++) {
            const ulonglong2 k0 = *reinterpret_cast<const ulonglong2*>(&kvT_s[2*h  ][v0]);
            const ulonglong2 k1 = *reinterpret_cast<const ulonglong2*>(&kvT_s[2*h+1][v0]);
            u64 s01 = fma2(qd[2*h], k0.x, mul2(qd[2*h+1], k1.x));
            u64 s23 = fma2(qd[2*h], k0.y, mul2(qd[2*h+1], k1.y));
            float s0, s1, s2, s3;
            unpack2(s01, s0, s1); unpack2(s23, s2, s3);
            const float p0 = ex2f(s0), p1 = ex2f(s1),
                        p2 = ex2f(s2), p3 = ex2f(s3);
            const u64 pp01 = pack2(p0, p1), pp23 = pack2(p2, p3);
            lhp[h] = add2(lhp[h], add2(pp01, pp23));
            const ulonglong2 v0r = *reinterpret_cast<const ulonglong2*>(&kvT_s[NJ+2*h  ][v0]);
            const ulonglong2 v1r = *reinterpret_cast<const ulonglong2*>(&kvT_s[NJ+2*h+1][v0]);
            acp[2*h]   = fma2(pp01, v0r.x, acp[2*h]);
            acp[2*h]   = fma2(pp23, v0r.y, acp[2*h]);
            acp[2*h+1] = fma2(pp01, v1r.x, acp[2*h+1]);
            acp[2*h+1] = fma2(pp23, v1r.y, acp[2*h+1]);
        }
    }
    float lh[5], ac[NJ];
    #pragma unroll
    for (int h = 0; h < 5; h++) { float lo, hi; unpack2(lhp[h], lo, hi); lh[h] = lo + hi; }
    #pragma unroll
    for (int j = 0; j < NJ; j++) { float lo, hi; unpack2(acp[j], lo, hi); ac[j] = lo + hi; }

    float xr = (chv[0]+chv[1]+chv[2]+chv[3]+chv[4]) * 0.2f + bomean_s;
    #pragma unroll
    for (int h = 0; h < 5; h++) {
        float inv = __fdividef(1.f, lh[h]);
        xr = fmaf(ac[2*h]  *inv, womean_s[2*h],   xr);
        xr = fmaf(ac[2*h+1]*inv, womean_s[2*h+1], xr);
    }

    float s1 = xr, s2 = xr*xr;
    #pragma unroll
    for (int o = 16; o > 0; o >>= 1) {
        s1 += __shfl_xor_sync(0xffffffffu, s1, o);
        s2 += __shfl_xor_sync(0xffffffffu, s2, o);
    }
    const int warp = u >> 5;
    if ((u & 31) == 0) { r1_s[warp] = s1; r2_s[warp] = s2; }
    __syncthreads();
    float S1 = 0.f, S2 = 0.f;
    #pragma unroll
    for (int w = 0; w < 6; w++) { S1 += r1_s[w]; S2 += r2_s[w]; }
    const float mu  = S1 * (1.f/NU);
    const float var = S2 * (1.f/NU) - mu*mu;
    const float o   = (xr - mu) * rsqrtf(var + 1e-3f) * gng[c] + gnb[c]
                      + pos[c*NU + u];
    g_xg[((size_t)b*NC + c)*NU + u] = o;
}

// ---------------------------------------------------------------------------
// K2: q2/k2/v2 = xg @ gW{q,k,v} + b. Weight loads batched 8-deep for MLP.
// ---------------------------------------------------------------------------
__global__ __launch_bounds__(NU) void k2_qkv(
    const float* __restrict__ gWq, const float* __restrict__ gbq,
    const float* __restrict__ gWk, const float* __restrict__ gbk,
    const float* __restrict__ gWv, const float* __restrict__ gbv)
{
    const int b  = blockIdx.y;
    const int t0 = blockIdx.x * TOK;
    const int u  = threadIdx.x;
    __shared__ float xrow[TOK][NU];
    for (int i = u; i < TOK*NU; i += NU)
        xrow[i/NU][i%NU] = g_xg[((size_t)b*NC + t0 + i/NU)*NU + (i%NU)];
    __syncthreads();

    float qa[TOK], ka[TOK], va[TOK];
    const float bqv = gbq[u], bkv = gbk[u], bvv = gbv[u];
    #pragma unroll
    for (int t = 0; t < TOK; t++) { qa[t]=bqv; ka[t]=bkv; va[t]=bvv; }
    for (int i0 = 0; i0 < NU; i0 += 8) {
        float wq[8], wk[8], wv[8];
        #pragma unroll
        for (int j = 0; j < 8; j++) {
            wq[j] = gWq[(i0+j)*NU+u];
            wk[j] = gWk[(i0+j)*NU+u];
            wv[j] = gWv[(i0+j)*NU+u];
        }
        #pragma unroll
        for (int j = 0; j < 8; j++) {
            #pragma unroll
            for (int t = 0; t < TOK; t++) {
                const float xv = xrow[t][i0+j];
                qa[t] = fmaf(xv, wq[j], qa[t]);
                ka[t] = fmaf(xv, wk[j], ka[t]);
                va[t] = fmaf(xv, wv[j], va[t]);
            }
        }
    }
    #pragma unroll
    for (int t = 0; t < TOK; t++) {
        const size_t off = ((size_t)b*NC + t0 + t)*NU + u;
        g_q2[off] = qa[t]; g_k2[off] = ka[t]; g_v2[off] = va[t];
    }
}

// ---------------------------------------------------------------------------
// K3: graph attention; AV loop loads batched 8-deep.
// ---------------------------------------------------------------------------
__global__ __launch_bounds__(256) void k3_attn()
{
    const int t0 = blockIdx.x * TT, h = blockIdx.y, b = blockIdx.z;
    const int tid = threadIdx.x;
    __shared__ __align__(16) float q_s[TT][NK2];
    __shared__ float p_s[TT][NC];

    for (int i = tid; i < TT*NK2; i += 256) {
        const int t = i / NK2, k = i % NK2;
        q_s[t][k] = g_q2[((size_t)b*NC + t0 + t)*NU + h*NK2 + k];
    }
    __syncthreads();

    const float sc = 0.14433756729740645f;   // 1/sqrt(48)
    for (int i = tid; i < TT*NC; i += 256) {
        const int t = i / NC, s = i % NC;
        const float4* kr = reinterpret_cast<const float4*>(
            g_k2 + ((size_t)b*NC + s)*NU + h*NK2);
        const float4* qq = reinterpret_cast<const float4*>(q_s[t]);
        float acc = 0.f;
        #pragma unroll
        for (int j = 0; j < NK2/4; j++) {
            float4 k4 = kr[j], q4 = qq[j];
            acc += q4.x*k4.x + q4.y*k4.y + q4.z*k4.z + q4.w*k4.w;
        }
        p_s[t][s] = acc * sc;
    }
    __syncthreads();

    {
        const int w = tid >> 5, lane = tid & 31;
        float m = -1e30f;
        for (int s = lane; s < NC; s += 32) m = fmaxf(m, p_s[w][s]);
        #pragma unroll
        for (int o = 16; o > 0; o >>= 1)
            m = fmaxf(m, __shfl_xor_sync(0xffffffffu, m, o));
        float l = 0.f;
        for (int s = lane; s < NC; s += 32) {
            const float e = __expf(p_s[w][s] - m);
            p_s[w][s] = e; l += e;
        }
        #pragma unroll
        for (int o = 16; o > 0; o >>= 1)
            l += __shfl_xor_sync(0xffffffffu, l, o);
        const float inv = __fdividef(1.f, l);
        for (int s = lane; s < NC; s += 32) p_s[w][s] *= inv;
    }
    __syncthreads();

    // AV with 8-deep batched V loads (strided gmem, independent)
    for (int i = tid; i < TT*NK2; i += 256) {
        const int t = i / NK2, k = i % NK2;
        const float* vb = g_v2 + (size_t)b*NC*NU + h*NK2 + k;
        float acc = 0.f;
        for (int s0 = 0; s0 < NC; s0 += 8) {   // 200 = 25*8
            float vv[8];
            #pragma unroll
            for (int j = 0; j < 8; j++) vv[j] = vb[(size_t)(s0+j)*NU];
            #pragma unroll
            for (int j = 0; j < 8; j++) acc = fmaf(p_s[t][s0+j], vv[j], acc);
        }
        g_att[((size_t)b*NC + t0 + t)*NU + h*NK2 + k] = acc;
    }
}

// ---------------------------------------------------------------------------
// K4: out-proj + residual + LN1. Weight loads batched 16-deep.
// ---------------------------------------------------------------------------
__global__ __launch_bounds__(NU) void k4_proj_ln1(
    const float* __restrict__ gWo, const float* __restrict__ gbo,
    const float* __restrict__ ln1g, const float* __restrict__ ln1b)
{
    const int b = blockIdx.y, t0 = blockIdx.x*TOK, u = threadIdx.x;
    __shared__ float arow[TOK][NU];
    __shared__ float r1s[6][TOK], r2s[6][TOK];
    for (int i = u; i < TOK*NU; i += NU)
        arow[i/NU][i%NU] = g_att[((size_t)b*NC + t0 + i/NU)*NU + (i%NU)];
    __syncthreads();

    float acc[TOK];
    const float bv = gbo[u];
    #pragma unroll
    for (int t = 0; t < TOK; t++) acc[t] = bv;
    for (int i0 = 0; i0 < NU; i0 += 16) {
        float w[16];
        #pragma unroll
        for (int j = 0; j < 16; j++) w[j] = gWo[(i0+j)*NU + u];
        #pragma unroll
        for (int j = 0; j < 16; j++) {
            #pragma unroll
            for (int t = 0; t < TOK; t++)
                acc[t] = fmaf(arow[t][i0+j], w[j], acc[t]);
        }
    }
    float y[TOK], s1[TOK], s2[TOK];
    #pragma unroll
    for (int t = 0; t < TOK; t++) {
        y[t] = g_xg[((size_t)b*NC + t0 + t)*NU + u] + acc[t];
        s1[t] = y[t]; s2[t] = y[t]*y[t];
    }
    #pragma unroll
    for (int o = 16; o > 0; o >>= 1) {
        #pragma unroll
        for (int t = 0; t < TOK; t++) {
            s1[t] += __shfl_xor_sync(0xffffffffu, s1[t], o);
            s2[t] += __shfl_xor_sync(0xffffffffu, s2[t], o);
        }
    }
    const int warp = u >> 5;
    if ((u & 31) == 0) {
        #pragma unroll
        for (int t = 0; t < TOK; t++) { r1s[warp][t] = s1[t]; r2s[warp][t] = s2[t]; }
    }
    __syncthreads();
    const float g = ln1g[u], bb = ln1b[u];
    #pragma unroll
    for (int t = 0; t < TOK; t++) {
        float S1 = 0.f, S2 = 0.f;
        #pragma unroll
        for (int w2 = 0; w2 < 6; w2++) { S1 += r1s[w2][t]; S2 += r2s[w2][t]; }
        const float mu = S1*(1.f/NU), var = S2*(1.f/NU) - mu*mu;
        g_xg1[((size_t)b*NC + t0 + t)*NU + u] =
            (y[t] - mu) * rsqrtf(var + 1e-3f) * g + bb;
    }
}

// ---------------------------------------------------------------------------
// K5: FFN + residual + LN2. Both gemms with 16-deep batched weight loads.
// ---------------------------------------------------------------------------
__global__ __launch_bounds__(NU) void k5_ffn_ln2(
    const float* __restrict__ W1, const float* __restrict__ b1,
    const float* __restrict__ W2, const float* __restrict__ b2,
    const float* __restrict__ ln2g, const float* __restrict__ ln2b,
    float* __restrict__ out)
{
    const int b = blockIdx.y, t0 = blockIdx.x*TOK, u = threadIdx.x;
    __shared__ float xrow[TOK][NU];
    __shared__ float h1[TOK][NU];
    __shared__ float r1s[6][TOK], r2s[6][TOK];
    for (int i = u; i < TOK*NU; i += NU)
        xrow[i/NU][i%NU] = g_xg1[((size_t)b*NC + t0 + i/NU)*NU + (i%NU)];
    __syncthreads();

    float acc[TOK];
    const float bv1 = b1[u];
    #pragma unroll
    for (int t = 0; t < TOK; t++) acc[t] = bv1;
    for (int i0 = 0; i0 < NU; i0 += 16) {
        float w[16];
        #pragma unroll
        for (int j = 0; j < 16; j++) w[j] = W1[(i0+j)*NU + u];
        #pragma unroll
        for (int j = 0; j < 16; j++) {
            #pragma unroll
            for (int t = 0; t < TOK; t++)
                acc[t] = fmaf(xrow[t][i0+j], w[j], acc[t]);
        }
    }
    #pragma unroll
    for (int t = 0; t < TOK; t++) h1[t][u] = acc[t];
    __syncthreads();

    const float bv2 = b2[u];
    #pragma unroll
    for (int t = 0; t < TOK; t++) acc[t] = bv2;
    for (int i0 = 0; i0 < NU; i0 += 16) {
        float w[16];
        #pragma unroll
        for (int j = 0; j < 16; j++) w[j] = W2[(i0+j)*NU + u];
        #pragma unroll
        for (int j = 0; j < 16; j++) {
            #pragma unroll
            for (int t = 0; t < TOK; t++)
                acc[t] = fmaf(h1[t][i0+j], w[j], acc[t]);
        }
    }

    float y[TOK], s1[TOK], s2[TOK];
    #pragma unroll
    for (int t = 0; t < TOK; t++) {
        const float v = acc[t];
        const float gelu = 0.5f * v * (1.f + erff(v * 0.70710678118654752f));
        y[t] = xrow[t][u] + gelu;
        s1[t] = y[t]; s2[t] = y[t]*y[t];
    }
    #pragma unroll
    for (int o = 16; o > 0; o >>= 1) {
        #pragma unroll
        for (int t = 0; t < TOK; t++) {
            s1[t] += __shfl_xor_sync(0xffffffffu, s1[t], o);
            s2[t] += __shfl_xor_sync(0xffffffffu, s2[t], o);
        }
    }
    const int warp = u >> 5;
    if ((u & 31) == 0) {
        #pragma unroll
        for (int t = 0; t < TOK; t++) { r1s[warp][t] = s1[t]; r2s[warp][t] = s2[t]; }
    }
    __syncthreads();
    const float g = ln2g[u], bb = ln2b[u];
    #pragma unroll
    for (int t = 0; t < TOK; t++) {
        float S1 = 0.f, S2 = 0.f;
        #pragma unroll
        for (int w2 = 0; w2 < 6; w2++) { S1 += r1s[w2][t]; S2 += r2s[w2][t]; }
        const float mu = S1*(1.f/NU), var = S2*(1.f/NU) - mu*mu;
        out[((size_t)b*NC + t0 + t)*NU + u] =
            (y[t] - mu) * rsqrtf(var + 1e-3f) * g + bb;
    }
}

// ---------------------------------------------------------------------------
extern "C" void kernel_launch(void* const* d_in, const int* in_sizes, int n_in,
                              void* d_out, int out_size)
{
    (void)in_sizes; (void)n_in; (void)out_size;
    const float* x    = (const float*)d_in[0];
    const float* Wq   = (const float*)d_in[1];
    const float* bq   = (const float*)d_in[2];
    const float* Wk   = (const float*)d_in[3];
    const float* bk   = (const float*)d_in[4];
    const float* Wv   = (const float*)d_in[5];
    const float* bv   = (const float*)d_in[6];
    const float* Wo   = (const float*)d_in[7];
    const float* bo   = (const float*)d_in[8];
    const float* pos  = (const float*)d_in[9];
    const float* gWq  = (const float*)d_in[10];
    const float* gbq  = (const float*)d_in[11];
    const float* gWk  = (const float*)d_in[12];
    const float* gbk  = (const float*)d_in[13];
    const float* gWv  = (const float*)d_in[14];
    const float* gbv  = (const float*)d_in[15];
    const float* gWo  = (const float*)d_in[16];
    const float* gbo  = (const float*)d_in[17];
    const float* gng  = (const float*)d_in[18];
    const float* gnb  = (const float*)d_in[19];
    const float* W1   = (const float*)d_in[20];
    const float* b1   = (const float*)d_in[21];
    const float* W2   = (const float*)d_in[22];
    const float* b2   = (const float*)d_in[23];
    const float* ln1g = (const float*)d_in[24];
    const float* ln1b = (const float*)d_in[25];
    const float* ln2g = (const float*)d_in[26];
    const float* ln2b = (const float*)d_in[27];
    float* out = (float*)d_out;

    k1_chunk  <<<dim3(NC, NB),        NU>>>(x, Wq, bq, Wk, bk, Wv, bv, Wo, bo,
                                            pos, gng, gnb);
    k2_qkv    <<<dim3(NC/TOK, NB),    NU>>>(gWq, gbq, gWk, gbk, gWv, gbv);
    k3_attn   <<<dim3(NC/TT, NH2, NB), 256>>>();
    k4_proj_ln1<<<dim3(NC/TOK, NB),   NU>>>(gWo, gbo, ln1g, ln1b);
    k5_ffn_ln2<<<dim3(NC/TOK, NB),    NU>>>(W1, b1, W2, b2, ln2g, ln2b, out);
}